// round 1
// baseline (speedup 1.0000x reference)
#include <cuda_runtime.h>
#include <math.h>

#define B_     32768
#define D_IN_  256
#define D_OUT_ 256
#define E_     8
#define H_     512
#define GH_    128

// ---------------- scratch (static __device__, no allocation) ----------------
__device__ int   g_counts[E_];
__device__ int   g_list[E_ * B_];
__device__ float g_wlist[E_ * B_];

// ---------------- zero output + counters ----------------
__global__ void zero_kernel(float* __restrict__ out) {
    int i = blockIdx.x * blockDim.x + threadIdx.x;
    int stride = gridDim.x * blockDim.x;
    // B_*D_OUT_ floats = 2,097,152 float4
    float4* o4 = (float4*)out;
    const int n4 = (B_ * D_OUT_) / 4;
    for (int j = i; j < n4; j += stride) o4[j] = make_float4(0.f, 0.f, 0.f, 0.f);
    if (blockIdx.x == 0 && threadIdx.x < E_) g_counts[threadIdx.x] = 0;
}

// ---------------- gating: MLP -> top2 softmax renorm -> routed lists ----------------
// 256 blocks x 256 threads; each block handles 128 tokens (2 at a time).
// shared: gW1 transposed [128][260 pad] + x pair + hidden + small params.
#define GATE_SMEM_FLOATS 35224
__global__ void __launch_bounds__(256) gating_kernel(
    const float* __restrict__ x,  const float* __restrict__ gW1,
    const float* __restrict__ gb1, const float* __restrict__ gW2,
    const float* __restrict__ gb2)
{
    extern __shared__ float sm[];
    float* shw  = sm;            // [128][260] transposed gW1: 33280
    float* xs   = sm + 33280;    // [2][256]
    float* hid  = sm + 33792;    // [2][128]
    float* b1s  = sm + 34048;    // [128]
    float* w2s  = sm + 34176;    // [128*8]
    float* b2s  = sm + 35200;    // [8]
    float* logt = sm + 35208;    // [16]

    const int tid = threadIdx.x;
    // stage weights (gW1 row-major [256][128] -> transposed padded)
    for (int idx = tid; idx < 256 * 128; idx += 256) {
        int i = idx >> 7, j = idx & 127;
        shw[j * 260 + i] = gW1[idx];
    }
    if (tid < 128) b1s[tid] = gb1[tid];
    for (int idx = tid; idx < 128 * 8; idx += 256) w2s[idx] = gW2[idx];
    if (tid < 8) b2s[tid] = gb2[tid];
    __syncthreads();

    const int j    = tid & 127;
    const int half = tid >> 7;
    for (int p = 0; p < 64; ++p) {
        const int tbase = blockIdx.x * 128 + p * 2;
        const float* xr = x + (size_t)tbase * D_IN_;
        xs[tid]       = xr[tid];
        xs[tid + 256] = xr[tid + 256];
        __syncthreads();

        // hidden[j] = relu(x . gW1[:,j] + b1[j])
        float acc = 0.f;
        const float4* wr4 = (const float4*)(shw + j * 260);
        const float4* xr4 = (const float4*)(xs + half * 256);
        #pragma unroll
        for (int i4 = 0; i4 < 64; ++i4) {
            float4 w = wr4[i4];
            float4 v = xr4[i4];
            acc = fmaf(w.x, v.x, fmaf(w.y, v.y, fmaf(w.z, v.z, fmaf(w.w, v.w, acc))));
        }
        hid[half * 128 + j] = fmaxf(acc + b1s[j], 0.f);
        __syncthreads();

        // logits (8 per token)
        if (j < 8) {
            float a = b2s[j];
            const float* hrow = hid + half * 128;
            #pragma unroll 8
            for (int h = 0; h < 128; ++h) a = fmaf(hrow[h], w2s[h * 8 + j], a);
            logt[half * 8 + j] = a;
        }
        __syncthreads();

        // top-2 + renormalized softmax weights; append to expert lists
        if (j == 0) {
            float l[8];
            #pragma unroll
            for (int q = 0; q < 8; ++q) l[q] = logt[half * 8 + q];
            int i1 = 0; float m1 = l[0];
            #pragma unroll
            for (int q = 1; q < 8; ++q) if (l[q] > m1) { m1 = l[q]; i1 = q; }
            int i2 = -1; float m2 = -1e30f;
            #pragma unroll
            for (int q = 0; q < 8; ++q) if (q != i1 && l[q] > m2) { m2 = l[q]; i2 = q; }
            const int t = tbase + half;
            const float ex  = expf(m2 - m1);
            const float den = 1.f + ex;
            int p1 = atomicAdd(&g_counts[i1], 1);
            g_list[i1 * B_ + p1] = t;  g_wlist[i1 * B_ + p1] = 1.f / den;
            int p2 = atomicAdd(&g_counts[i2], 1);
            g_list[i2 * B_ + p2] = t;  g_wlist[i2 * B_ + p2] = ex / den;
        }
        __syncthreads();
    }
}

// ---------------- expert MLP: 3 layers fused, 32-token tiles ----------------
// grid (1024, 8); 256 threads; dyn shared 96KB -> 2 blocks/SM.
#define EXP_SMEM_BYTES 98304
__global__ void __launch_bounds__(256, 2) expert_kernel(
    const float* __restrict__ x,
    const float* __restrict__ We1, const float* __restrict__ be1,
    const float* __restrict__ We2, const float* __restrict__ be2,
    const float* __restrict__ We3, const float* __restrict__ be3,
    float* __restrict__ out)
{
    const int e = blockIdx.y;
    const int n = g_counts[e];
    const int row0 = blockIdx.x << 5;
    if (row0 >= n) return;

    extern __shared__ float sm[];
    float* xs = sm;           // [32][256]
    float* hs = sm + 8192;    // [32][512] (reused for h1 then h2)
    __shared__ int   toks[32];
    __shared__ float twt[32];

    const int tid = threadIdx.x;
    if (tid < 32) {
        int r = row0 + tid;
        if (r < n) { toks[tid] = g_list[e * B_ + r]; twt[tid] = g_wlist[e * B_ + r]; }
        else       { toks[tid] = -1;                 twt[tid] = 0.f; }
    }
    __syncthreads();

    // gather x tile (zeros for inactive rows)
    for (int v = tid; v < 32 * 64; v += 256) {
        int m = v >> 6, c = v & 63;
        int t = toks[m];
        float4 val = (t >= 0) ? ((const float4*)(x + (size_t)t * D_IN_))[c]
                              : make_float4(0.f, 0.f, 0.f, 0.f);
        ((float4*)xs)[m * 64 + c] = val;
    }
    __syncthreads();

    float acc0[32], acc1[32];
    const int j0 = tid, j1 = tid + 256;

    // ---- layer 1: [32,256] @ [256,512] ----
    {
        const float* W1 = We1 + ((size_t)e << 17);
        #pragma unroll
        for (int m = 0; m < 32; ++m) { acc0[m] = 0.f; acc1[m] = 0.f; }
        #pragma unroll 1
        for (int k = 0; k < 256; k += 4) {
            const float* wp = W1 + (size_t)k * 512;
            float wa0 = wp[j0], wa1 = wp[512 + j0], wa2 = wp[1024 + j0], wa3 = wp[1536 + j0];
            float wb0 = wp[j1], wb1 = wp[512 + j1], wb2 = wp[1024 + j1], wb3 = wp[1536 + j1];
            #pragma unroll
            for (int m = 0; m < 32; ++m) {
                float4 v = ((const float4*)(xs + m * 256))[k >> 2];
                acc0[m] = fmaf(v.x, wa0, fmaf(v.y, wa1, fmaf(v.z, wa2, fmaf(v.w, wa3, acc0[m]))));
                acc1[m] = fmaf(v.x, wb0, fmaf(v.y, wb1, fmaf(v.z, wb2, fmaf(v.w, wb3, acc1[m]))));
            }
        }
        const float ba = be1[e * H_ + j0], bb = be1[e * H_ + j1];
        #pragma unroll
        for (int m = 0; m < 32; ++m) {
            hs[m * 512 + j0] = fmaxf(acc0[m] + ba, 0.f);
            hs[m * 512 + j1] = fmaxf(acc1[m] + bb, 0.f);
        }
    }
    __syncthreads();

    // ---- layer 2: [32,512] @ [512,512] ----
    {
        const float* W2 = We2 + ((size_t)e << 18);
        #pragma unroll
        for (int m = 0; m < 32; ++m) { acc0[m] = 0.f; acc1[m] = 0.f; }
        #pragma unroll 1
        for (int k = 0; k < 512; k += 4) {
            const float* wp = W2 + (size_t)k * 512;
            float wa0 = wp[j0], wa1 = wp[512 + j0], wa2 = wp[1024 + j0], wa3 = wp[1536 + j0];
            float wb0 = wp[j1], wb1 = wp[512 + j1], wb2 = wp[1024 + j1], wb3 = wp[1536 + j1];
            #pragma unroll
            for (int m = 0; m < 32; ++m) {
                float4 v = ((const float4*)(hs + m * 512))[k >> 2];
                acc0[m] = fmaf(v.x, wa0, fmaf(v.y, wa1, fmaf(v.z, wa2, fmaf(v.w, wa3, acc0[m]))));
                acc1[m] = fmaf(v.x, wb0, fmaf(v.y, wb1, fmaf(v.z, wb2, fmaf(v.w, wb3, acc1[m]))));
            }
        }
        __syncthreads();  // all reads of h1 done before overwrite
        const float ba = be2[e * H_ + j0], bb = be2[e * H_ + j1];
        #pragma unroll
        for (int m = 0; m < 32; ++m) {
            hs[m * 512 + j0] = fmaxf(acc0[m] + ba, 0.f);
            hs[m * 512 + j1] = fmaxf(acc1[m] + bb, 0.f);
        }
    }
    __syncthreads();

    // ---- layer 3: [32,512] @ [512,256] + weighted combine ----
    {
        const float* W3 = We3 + ((size_t)e << 17);
        float acc[32];
        #pragma unroll
        for (int m = 0; m < 32; ++m) acc[m] = 0.f;
        #pragma unroll 1
        for (int k = 0; k < 512; k += 4) {
            const float* wp = W3 + (size_t)k * 256;
            float w0 = wp[tid], w1 = wp[256 + tid], w2 = wp[512 + tid], w3 = wp[768 + tid];
            #pragma unroll
            for (int m = 0; m < 32; ++m) {
                float4 v = ((const float4*)(hs + m * 512))[k >> 2];
                acc[m] = fmaf(v.x, w0, fmaf(v.y, w1, fmaf(v.z, w2, fmaf(v.w, w3, acc[m]))));
            }
        }
        const float b3 = be3[e * D_OUT_ + tid];
        #pragma unroll
        for (int m = 0; m < 32; ++m) {
            int t = toks[m];
            if (t >= 0)
                atomicAdd(out + (size_t)t * D_OUT_ + tid, (acc[m] + b3) * twt[m]);
        }
    }
}

// ---------------- aux outputs ----------------
__global__ void finalize_kernel(float* __restrict__ out) {
    __shared__ float us[E_];
    const int e = threadIdx.x;
    if (e < E_) {
        float u = (float)g_counts[e] / (float)B_;
        us[e] = u;
        out[(size_t)B_ * D_OUT_ + 1 + e] = u;   // expert_usage
    }
    __syncthreads();
    if (e == 0) {
        float s = 0.f;
        #pragma unroll
        for (int i = 0; i < E_; ++i) { float d = us[i] - (1.f / E_); s += d * d; }
        out[(size_t)B_ * D_OUT_] = (s / E_) * 0.01f;  // balance_loss
    }
}

// ---------------- launch ----------------
extern "C" void kernel_launch(void* const* d_in, const int* in_sizes, int n_in,
                              void* d_out, int out_size) {
    const float* x   = (const float*)d_in[0];
    const float* gW1 = (const float*)d_in[1];
    const float* gb1 = (const float*)d_in[2];
    const float* gW2 = (const float*)d_in[3];
    const float* gb2 = (const float*)d_in[4];
    const float* We1 = (const float*)d_in[5];
    const float* be1 = (const float*)d_in[6];
    const float* We2 = (const float*)d_in[7];
    const float* be2 = (const float*)d_in[8];
    const float* We3 = (const float*)d_in[9];
    const float* be3 = (const float*)d_in[10];
    float* out = (float*)d_out;

    cudaFuncSetAttribute(gating_kernel, cudaFuncAttributeMaxDynamicSharedMemorySize,
                         GATE_SMEM_FLOATS * 4);
    cudaFuncSetAttribute(expert_kernel, cudaFuncAttributeMaxDynamicSharedMemorySize,
                         EXP_SMEM_BYTES);

    zero_kernel<<<512, 256>>>(out);
    gating_kernel<<<256, 256, GATE_SMEM_FLOATS * 4>>>(x, gW1, gb1, gW2, gb2);
    dim3 eg(1024, 8);
    expert_kernel<<<eg, 256, EXP_SMEM_BYTES>>>(x, We1, be1, We2, be2, We3, be3, out);
    finalize_kernel<<<1, 32>>>(out);
}

// round 3
// speedup vs baseline: 3.5406x; 3.5406x over previous
#include <cuda_runtime.h>
#include <stdint.h>
#include <math.h>

#define B_     32768
#define D_IN_  256
#define D_OUT_ 256
#define E_     8
#define H_     512
#define GH_    128
#define CAP_   32768

// ---------------- scratch (static __device__, no allocation) ----------------
__device__ int   g_counts[E_];
__device__ int   g_list[E_ * B_];
__device__ float g_wlist[E_ * B_];
__device__ float g_xg[(size_t)E_ * CAP_ * D_IN_];   // gathered inputs per expert
__device__ float g_h1[(size_t)E_ * CAP_ * H_];      // layer-1 activations
__device__ float g_h2[(size_t)E_ * CAP_ * H_];      // layer-2 activations

// ---------------- zero output + counters ----------------
__global__ void zero_kernel(float* __restrict__ out) {
    int i = blockIdx.x * blockDim.x + threadIdx.x;
    int stride = gridDim.x * blockDim.x;
    float4* o4 = (float4*)out;
    const int n4 = (B_ * D_OUT_) / 4;
    for (int j = i; j < n4; j += stride) o4[j] = make_float4(0.f, 0.f, 0.f, 0.f);
    if (blockIdx.x == 0 && threadIdx.x < E_) g_counts[threadIdx.x] = 0;
}

// ---------------- gating: MLP -> top2 softmax renorm -> routed lists ----------------
#define GATE_SMEM_FLOATS 35224
__global__ void __launch_bounds__(256) gating_kernel(
    const float* __restrict__ x,  const float* __restrict__ gW1,
    const float* __restrict__ gb1, const float* __restrict__ gW2,
    const float* __restrict__ gb2)
{
    extern __shared__ float sm[];
    float* shw  = sm;            // [128][260] transposed gW1
    float* xs   = sm + 33280;    // [2][256]
    float* hid  = sm + 33792;    // [2][128]
    float* b1s  = sm + 34048;    // [128]
    float* w2s  = sm + 34176;    // [128*8]
    float* b2s  = sm + 35200;    // [8]
    float* logt = sm + 35208;    // [16]

    const int tid = threadIdx.x;
    for (int idx = tid; idx < 256 * 128; idx += 256) {
        int i = idx >> 7, j = idx & 127;
        shw[j * 260 + i] = gW1[idx];
    }
    if (tid < 128) b1s[tid] = gb1[tid];
    for (int idx = tid; idx < 128 * 8; idx += 256) w2s[idx] = gW2[idx];
    if (tid < 8) b2s[tid] = gb2[tid];
    __syncthreads();

    const int j    = tid & 127;
    const int half = tid >> 7;
    for (int p = 0; p < 64; ++p) {
        const int tbase = blockIdx.x * 128 + p * 2;
        const float* xr = x + (size_t)tbase * D_IN_;
        xs[tid]       = xr[tid];
        xs[tid + 256] = xr[tid + 256];
        __syncthreads();

        float acc = 0.f;
        const float4* wr4 = (const float4*)(shw + j * 260);
        const float4* xr4 = (const float4*)(xs + half * 256);
        #pragma unroll
        for (int i4 = 0; i4 < 64; ++i4) {
            float4 w = wr4[i4];
            float4 v = xr4[i4];
            acc = fmaf(w.x, v.x, fmaf(w.y, v.y, fmaf(w.z, v.z, fmaf(w.w, v.w, acc))));
        }
        hid[half * 128 + j] = fmaxf(acc + b1s[j], 0.f);
        __syncthreads();

        if (j < 8) {
            float a = b2s[j];
            const float* hrow = hid + half * 128;
            #pragma unroll 8
            for (int h = 0; h < 128; ++h) a = fmaf(hrow[h], w2s[h * 8 + j], a);
            logt[half * 8 + j] = a;
        }
        __syncthreads();

        if (j == 0) {
            float l[8];
            #pragma unroll
            for (int q = 0; q < 8; ++q) l[q] = logt[half * 8 + q];
            int i1 = 0; float m1 = l[0];
            #pragma unroll
            for (int q = 1; q < 8; ++q) if (l[q] > m1) { m1 = l[q]; i1 = q; }
            int i2 = -1; float m2 = -1e30f;
            #pragma unroll
            for (int q = 0; q < 8; ++q) if (q != i1 && l[q] > m2) { m2 = l[q]; i2 = q; }
            const int t = tbase + half;
            const float ex  = expf(m2 - m1);
            const float den = 1.f + ex;
            int p1 = atomicAdd(&g_counts[i1], 1);
            g_list[i1 * B_ + p1] = t;  g_wlist[i1 * B_ + p1] = 1.f / den;
            int p2 = atomicAdd(&g_counts[i2], 1);
            g_list[i2 * B_ + p2] = t;  g_wlist[i2 * B_ + p2] = ex / den;
        }
        __syncthreads();
    }
}

// ---------------- gather x rows into per-expert contiguous segments ----------------
__global__ void __launch_bounds__(256) gather_kernel(const float* __restrict__ x) {
    const int e = blockIdx.y;
    const int n = g_counts[e];
    const int row0 = blockIdx.x * 64;
    if (row0 >= n) return;
    for (int v = threadIdx.x; v < 64 * 64; v += 256) {
        int r = row0 + (v >> 6);
        if (r < n) {
            int t = g_list[e * B_ + r];
            ((float4*)(g_xg + ((size_t)e * CAP_ + r) * D_IN_))[v & 63] =
                ((const float4*)(x + (size_t)t * D_IN_))[v & 63];
        }
    }
}

// ---------------- tf32 tensor-core GEMM ----------------
#define BM 128
#define BN 128
#define BK 16
#define AP 20    // padded A smem stride (uint32 elems)
#define WP 136   // padded W smem stride

__device__ __forceinline__ uint32_t f2tf(float x) {
    uint32_t u;
    asm("cvt.rna.tf32.f32 %0, %1;" : "=r"(u) : "f"(x));
    return u;
}
__device__ __forceinline__ uint4 f4tf(float4 v) {
    uint4 u; u.x = f2tf(v.x); u.y = f2tf(v.y); u.z = f2tf(v.z); u.w = f2tf(v.w);
    return u;
}
__device__ __forceinline__ void mma8(float* d, const uint32_t* a, const uint32_t* b) {
    asm volatile(
        "mma.sync.aligned.m16n8k8.row.col.f32.tf32.tf32.f32 "
        "{%0,%1,%2,%3},{%4,%5,%6,%7},{%8,%9},{%0,%1,%2,%3};\n"
        : "+f"(d[0]), "+f"(d[1]), "+f"(d[2]), "+f"(d[3])
        : "r"(a[0]), "r"(a[1]), "r"(a[2]), "r"(a[3]), "r"(b[0]), "r"(b[1]));
}

// STAGE: 1 -> A=g_xg, Y=g_h1; 2 -> A=g_h1, Y=g_h2; 3 -> A=g_h2, Y=out (scatter)
template<int STAGE, int K, int N, int LDA, bool RELU, bool SCATTER>
__global__ void __launch_bounds__(256) gemm_tf32(
    const float* __restrict__ W, const float* __restrict__ bias,
    float* __restrict__ Yout)
{
    const int e = blockIdx.z;
    const int cnt = g_counts[e];
    const int row0 = blockIdx.x * BM;
    if (row0 >= cnt) return;
    const int n0 = blockIdx.y * BN;

    __shared__ uint32_t As[2][BM * AP];
    __shared__ uint32_t Ws[2][BK * WP];
    __shared__ int   stok[BM];
    __shared__ float swt[BM];

    const float* A = (STAGE == 1) ? g_xg : (STAGE == 2) ? g_h1 : g_h2;
    float* Y = SCATTER ? Yout : ((STAGE == 1) ? g_h1 : g_h2);

    const int tid  = threadIdx.x;
    const int lane = tid & 31;
    const int wid  = tid >> 5;
    const int g  = lane >> 2, tg = lane & 3;
    const int wm = wid >> 2,  wn = wid & 3;       // 2 x 4 warps
    const int mb = wm * 64,   nb = wn * 32;

    if (SCATTER) {
        if (tid < BM) {
            int r = row0 + tid;
            stok[tid] = (r < cnt) ? g_list[e * B_ + r] : -1;
            swt[tid]  = (r < cnt) ? g_wlist[e * B_ + r] : 0.f;
        }
    }

    const float* Ab = A + ((size_t)e * CAP_ + row0) * LDA;
    const float* Wb = W + (size_t)e * K * N + n0;

    // staging coordinates (each thread: 2 float4 of A, 2 float4 of W per tile)
    const int arow = tid >> 2;          // 0..63  (second slot: +64)
    const int acol = (tid & 3) * 4;     // 0,4,8,12
    const int wrow = tid >> 5;          // 0..7   (second slot: +8)
    const int wcol = (tid & 31) * 4;    // 0..124

    const bool av0 = (row0 + arow) < cnt;
    const bool av1 = (row0 + arow + 64) < cnt;
    const float4 z4 = make_float4(0.f, 0.f, 0.f, 0.f);

    float acc[4][4][4];
    #pragma unroll
    for (int f = 0; f < 4; ++f)
        #pragma unroll
        for (int j = 0; j < 4; ++j)
            #pragma unroll
            for (int q = 0; q < 4; ++q) acc[f][j][q] = 0.f;

    const int KT = K / BK;

    // prologue: tile 0
    float4 aR0 = av0 ? *(const float4*)(Ab + (size_t)arow * LDA + acol) : z4;
    float4 aR1 = av1 ? *(const float4*)(Ab + (size_t)(arow + 64) * LDA + acol) : z4;
    float4 wR0 = *(const float4*)(Wb + (size_t)wrow * N + wcol);
    float4 wR1 = *(const float4*)(Wb + (size_t)(wrow + 8) * N + wcol);
    *(uint4*)&As[0][arow * AP + acol]        = f4tf(aR0);
    *(uint4*)&As[0][(arow + 64) * AP + acol] = f4tf(aR1);
    *(uint4*)&Ws[0][wrow * WP + wcol]        = f4tf(wR0);
    *(uint4*)&Ws[0][(wrow + 8) * WP + wcol]  = f4tf(wR1);
    __syncthreads();

    for (int kt = 0; kt < KT; ++kt) {
        const int cur = kt & 1;
        if (kt + 1 < KT) {
            const int ko = (kt + 1) * BK;
            aR0 = av0 ? *(const float4*)(Ab + (size_t)arow * LDA + ko + acol) : z4;
            aR1 = av1 ? *(const float4*)(Ab + (size_t)(arow + 64) * LDA + ko + acol) : z4;
            wR0 = *(const float4*)(Wb + (size_t)(ko + wrow) * N + wcol);
            wR1 = *(const float4*)(Wb + (size_t)(ko + wrow + 8) * N + wcol);
        }

        #pragma unroll
        for (int ks = 0; ks < 2; ++ks) {
            const int kk = ks * 8;
            uint32_t af[4][4];
            uint32_t bf[4][2];
            #pragma unroll
            for (int f = 0; f < 4; ++f) {
                int r = mb + f * 16 + g;
                af[f][0] = As[cur][r * AP + kk + tg];
                af[f][1] = As[cur][(r + 8) * AP + kk + tg];
                af[f][2] = As[cur][r * AP + kk + tg + 4];
                af[f][3] = As[cur][(r + 8) * AP + kk + tg + 4];
            }
            #pragma unroll
            for (int j = 0; j < 4; ++j) {
                int c = nb + j * 8 + g;
                bf[j][0] = Ws[cur][(kk + tg) * WP + c];
                bf[j][1] = Ws[cur][(kk + tg + 4) * WP + c];
            }
            #pragma unroll
            for (int f = 0; f < 4; ++f)
                #pragma unroll
                for (int j = 0; j < 4; ++j)
                    mma8(acc[f][j], af[f], bf[j]);
        }

        if (kt + 1 < KT) {
            const int nxt = cur ^ 1;
            *(uint4*)&As[nxt][arow * AP + acol]        = f4tf(aR0);
            *(uint4*)&As[nxt][(arow + 64) * AP + acol] = f4tf(aR1);
            *(uint4*)&Ws[nxt][wrow * WP + wcol]        = f4tf(wR0);
            *(uint4*)&Ws[nxt][(wrow + 8) * WP + wcol]  = f4tf(wR1);
            __syncthreads();
        }
    }

    // epilogue
    const float* Bb = bias + e * N + n0;
    #pragma unroll
    for (int f = 0; f < 4; ++f) {
        const int rl = mb + f * 16 + g;          // local rows rl, rl+8
        #pragma unroll
        for (int j = 0; j < 4; ++j) {
            const int c = nb + j * 8 + 2 * tg;
            const float b0 = Bb[c], b1 = Bb[c + 1];
            float v00 = acc[f][j][0] + b0, v01 = acc[f][j][1] + b1;
            float v10 = acc[f][j][2] + b0, v11 = acc[f][j][3] + b1;
            if (RELU) {
                v00 = fmaxf(v00, 0.f); v01 = fmaxf(v01, 0.f);
                v10 = fmaxf(v10, 0.f); v11 = fmaxf(v11, 0.f);
            }
            if (!SCATTER) {
                if (row0 + rl < cnt) {
                    float* p = Y + ((size_t)e * CAP_ + row0 + rl) * N + n0 + c;
                    p[0] = v00; p[1] = v01;
                }
                if (row0 + rl + 8 < cnt) {
                    float* p = Y + ((size_t)e * CAP_ + row0 + rl + 8) * N + n0 + c;
                    p[0] = v10; p[1] = v11;
                }
            } else {
                int t0 = stok[rl];
                if (t0 >= 0) {
                    float w0 = swt[rl];
                    atomicAdd(Y + (size_t)t0 * D_OUT_ + n0 + c,     v00 * w0);
                    atomicAdd(Y + (size_t)t0 * D_OUT_ + n0 + c + 1, v01 * w0);
                }
                int t1 = stok[rl + 8];
                if (t1 >= 0) {
                    float w1 = swt[rl + 8];
                    atomicAdd(Y + (size_t)t1 * D_OUT_ + n0 + c,     v10 * w1);
                    atomicAdd(Y + (size_t)t1 * D_OUT_ + n0 + c + 1, v11 * w1);
                }
            }
        }
    }
}

// ---------------- aux outputs ----------------
__global__ void finalize_kernel(float* __restrict__ out) {
    __shared__ float us[E_];
    const int e = threadIdx.x;
    if (e < E_) {
        float u = (float)g_counts[e] / (float)B_;
        us[e] = u;
        out[(size_t)B_ * D_OUT_ + 1 + e] = u;
    }
    __syncthreads();
    if (e == 0) {
        float s = 0.f;
        #pragma unroll
        for (int i = 0; i < E_; ++i) { float d = us[i] - (1.f / E_); s += d * d; }
        out[(size_t)B_ * D_OUT_] = (s / E_) * 0.01f;
    }
}

// ---------------- launch ----------------
extern "C" void kernel_launch(void* const* d_in, const int* in_sizes, int n_in,
                              void* d_out, int out_size) {
    const float* x   = (const float*)d_in[0];
    const float* gW1 = (const float*)d_in[1];
    const float* gb1 = (const float*)d_in[2];
    const float* gW2 = (const float*)d_in[3];
    const float* gb2 = (const float*)d_in[4];
    const float* We1 = (const float*)d_in[5];
    const float* be1 = (const float*)d_in[6];
    const float* We2 = (const float*)d_in[7];
    const float* be2 = (const float*)d_in[8];
    const float* We3 = (const float*)d_in[9];
    const float* be3 = (const float*)d_in[10];
    float* out = (float*)d_out;

    cudaFuncSetAttribute(gating_kernel, cudaFuncAttributeMaxDynamicSharedMemorySize,
                         GATE_SMEM_FLOATS * 4);

    zero_kernel<<<512, 256>>>(out);
    gating_kernel<<<256, 256, GATE_SMEM_FLOATS * 4>>>(x, gW1, gb1, gW2, gb2);
    gather_kernel<<<dim3(CAP_ / 64, E_), 256>>>(x);

    // layer 1: [n_e,256] @ [256,512] -> relu -> h1
    gemm_tf32<1, 256, 512, 256, true, false>
        <<<dim3(CAP_ / BM, 512 / BN, E_), 256>>>(We1, be1, nullptr);
    // layer 2: [n_e,512] @ [512,512] -> relu -> h2
    gemm_tf32<2, 512, 512, 512, true, false>
        <<<dim3(CAP_ / BM, 512 / BN, E_), 256>>>(We2, be2, nullptr);
    // layer 3: [n_e,512] @ [512,256] -> +bias, *gate weight, scatter-add
    gemm_tf32<3, 512, 256, 512, false, true>
        <<<dim3(CAP_ / BM, 256 / BN, E_), 256>>>(We3, be3, out);

    finalize_kernel<<<1, 32>>>(out);
}

// round 5
// speedup vs baseline: 3.9503x; 1.1157x over previous
#include <cuda_runtime.h>
#include <stdint.h>
#include <math.h>

#define B_     32768
#define D_IN_  256
#define D_OUT_ 256
#define E_     8
#define H_     512
#define GH_    128
#define CAP_   32768

// ---------------- scratch (static __device__, no allocation) ----------------
__device__ int   g_counts[E_];
__device__ int   g_list[E_ * B_];
__device__ float g_wlist[E_ * B_];
__device__ float g_xg[(size_t)E_ * CAP_ * D_IN_];   // gathered inputs (tf32-rounded)
__device__ float g_h1[(size_t)E_ * CAP_ * H_];      // layer-1 activations (tf32-rounded)
__device__ float g_h2[(size_t)E_ * CAP_ * H_];      // layer-2 activations (tf32-rounded)
__device__ float g_wT1[(size_t)E_ * H_ * D_IN_];    // We1^T  [E][512][256] tf32-rounded
__device__ float g_wT2[(size_t)E_ * H_ * H_];       // We2^T  [E][512][512]
__device__ float g_wT3[(size_t)E_ * D_OUT_ * H_];   // We3^T  [E][256][512]

// ---------------- helpers ----------------
__device__ __forceinline__ uint32_t smem_u32(const void* p) {
    uint32_t a;
    asm("{ .reg .u64 t; cvta.to.shared.u64 t, %1; cvt.u32.u64 %0, t; }" : "=r"(a) : "l"(p));
    return a;
}
__device__ __forceinline__ uint32_t f2tf(float x) {
    uint32_t u;
    asm("cvt.rna.tf32.f32 %0, %1;" : "=r"(u) : "f"(x));
    return u;
}
__device__ __forceinline__ void cp16(uint32_t dst, const float* src) {
    asm volatile("cp.async.cg.shared.global [%0], [%1], 16;"
                 :: "r"(dst), "l"(__cvta_generic_to_global(src)) : "memory");
}
#define CP_COMMIT() asm volatile("cp.async.commit_group;" ::: "memory")
#define CP_WAIT1()  asm volatile("cp.async.wait_group 1;" ::: "memory")

__device__ __forceinline__ void ldsm4(uint32_t* r, uint32_t a) {
    asm volatile("ldmatrix.sync.aligned.m8n8.x4.shared.b16 {%0,%1,%2,%3}, [%4];"
                 : "=r"(r[0]), "=r"(r[1]), "=r"(r[2]), "=r"(r[3]) : "r"(a));
}
__device__ __forceinline__ void ldsm2(uint32_t* r, uint32_t a) {
    asm volatile("ldmatrix.sync.aligned.m8n8.x2.shared.b16 {%0,%1}, [%2];"
                 : "=r"(r[0]), "=r"(r[1]) : "r"(a));
}
__device__ __forceinline__ void mma8(float* d, const uint32_t* a, const uint32_t* b) {
    asm volatile(
        "mma.sync.aligned.m16n8k8.row.col.f32.tf32.tf32.f32 "
        "{%0,%1,%2,%3},{%4,%5,%6,%7},{%8,%9},{%0,%1,%2,%3};\n"
        : "+f"(d[0]), "+f"(d[1]), "+f"(d[2]), "+f"(d[3])
        : "r"(a[0]), "r"(a[1]), "r"(a[2]), "r"(a[3]), "r"(b[0]), "r"(b[1]));
}

// ---------------- zero output + counters ----------------
__global__ void zero_kernel(float* __restrict__ out) {
    int i = blockIdx.x * blockDim.x + threadIdx.x;
    int stride = gridDim.x * blockDim.x;
    float4* o4 = (float4*)out;
    const int n4 = (B_ * D_OUT_) / 4;
    for (int j = i; j < n4; j += stride) o4[j] = make_float4(0.f, 0.f, 0.f, 0.f);
    if (blockIdx.x == 0 && threadIdx.x < E_) g_counts[threadIdx.x] = 0;
}

// ---------------- gating (unchanged, proven) ----------------
#define GATE_SMEM_FLOATS 35224
__global__ void __launch_bounds__(256) gating_kernel(
    const float* __restrict__ x,  const float* __restrict__ gW1,
    const float* __restrict__ gb1, const float* __restrict__ gW2,
    const float* __restrict__ gb2)
{
    extern __shared__ float sm[];
    float* shw  = sm;
    float* xs   = sm + 33280;
    float* hid  = sm + 33792;
    float* b1s  = sm + 34048;
    float* w2s  = sm + 34176;
    float* b2s  = sm + 35200;
    float* logt = sm + 35208;

    const int tid = threadIdx.x;
    for (int idx = tid; idx < 256 * 128; idx += 256) {
        int i = idx >> 7, j = idx & 127;
        shw[j * 260 + i] = gW1[idx];
    }
    if (tid < 128) b1s[tid] = gb1[tid];
    for (int idx = tid; idx < 128 * 8; idx += 256) w2s[idx] = gW2[idx];
    if (tid < 8) b2s[tid] = gb2[tid];
    __syncthreads();

    const int j    = tid & 127;
    const int half = tid >> 7;
    for (int p = 0; p < 64; ++p) {
        const int tbase = blockIdx.x * 128 + p * 2;
        const float* xr = x + (size_t)tbase * D_IN_;
        xs[tid]       = xr[tid];
        xs[tid + 256] = xr[tid + 256];
        __syncthreads();

        float acc = 0.f;
        const float4* wr4 = (const float4*)(shw + j * 260);
        const float4* xr4 = (const float4*)(xs + half * 256);
        #pragma unroll
        for (int i4 = 0; i4 < 64; ++i4) {
            float4 w = wr4[i4];
            float4 v = xr4[i4];
            acc = fmaf(w.x, v.x, fmaf(w.y, v.y, fmaf(w.z, v.z, fmaf(w.w, v.w, acc))));
        }
        hid[half * 128 + j] = fmaxf(acc + b1s[j], 0.f);
        __syncthreads();

        if (j < 8) {
            float a = b2s[j];
            const float* hrow = hid + half * 128;
            #pragma unroll 8
            for (int h = 0; h < 128; ++h) a = fmaf(hrow[h], w2s[h * 8 + j], a);
            logt[half * 8 + j] = a;
        }
        __syncthreads();

        if (j == 0) {
            float l[8];
            #pragma unroll
            for (int q = 0; q < 8; ++q) l[q] = logt[half * 8 + q];
            int i1 = 0; float m1 = l[0];
            #pragma unroll
            for (int q = 1; q < 8; ++q) if (l[q] > m1) { m1 = l[q]; i1 = q; }
            int i2 = -1; float m2 = -1e30f;
            #pragma unroll
            for (int q = 0; q < 8; ++q) if (q != i1 && l[q] > m2) { m2 = l[q]; i2 = q; }
            const int t = tbase + half;
            const float ex  = expf(m2 - m1);
            const float den = 1.f + ex;
            int p1 = atomicAdd(&g_counts[i1], 1);
            g_list[i1 * B_ + p1] = t;  g_wlist[i1 * B_ + p1] = 1.f / den;
            int p2 = atomicAdd(&g_counts[i2], 1);
            g_list[i2 * B_ + p2] = t;  g_wlist[i2 * B_ + p2] = ex / den;
        }
        __syncthreads();
    }
}

// ---------------- gather x rows (tf32-rounded) ----------------
__global__ void __launch_bounds__(256) gather_kernel(const float* __restrict__ x) {
    const int e = blockIdx.y;
    const int n = g_counts[e];
    const int row0 = blockIdx.x * 64;
    if (row0 >= n) return;
    for (int v = threadIdx.x; v < 64 * 64; v += 256) {
        int r = row0 + (v >> 6);
        if (r < n) {
            int t = g_list[e * B_ + r];
            float4 s = ((const float4*)(x + (size_t)t * D_IN_))[v & 63];
            uint4 u;
            u.x = f2tf(s.x); u.y = f2tf(s.y); u.z = f2tf(s.z); u.w = f2tf(s.w);
            ((uint4*)(g_xg + ((size_t)e * CAP_ + r) * D_IN_))[v & 63] = u;
        }
    }
}

// ---------------- weight transpose + tf32 round:  out[e][n][k] = rna(in[e][k][n]) ----------------
__global__ void __launch_bounds__(256) transpose_kernel(const float* __restrict__ in, int sel,
                                                        int K, int N) {
    __shared__ float t[32][33];
    float* out = (sel == 1) ? g_wT1 : (sel == 2) ? g_wT2 : g_wT3;
    const int e = blockIdx.z;
    const int k0 = blockIdx.x * 32, n0 = blockIdx.y * 32;
    const float* I = in + (size_t)e * K * N;
    float* O = out + (size_t)e * K * N;
    const int tx = threadIdx.x & 31, ty = threadIdx.x >> 5;   // 32 x 8
    #pragma unroll
    for (int p = 0; p < 32; p += 8)
        t[ty + p][tx] = I[(size_t)(k0 + ty + p) * N + n0 + tx];
    __syncthreads();
    #pragma unroll
    for (int p = 0; p < 32; p += 8)
        O[(size_t)(n0 + ty + p) * K + k0 + tx] = __uint_as_float(f2tf(t[tx][ty + p]));
}

// ---------------- tf32 mma.sync GEMM, ldmatrix + cp.async ----------------
// Block 128x128, BK=32. Smem rows: 36 floats (144B) stride: 16B-aligned (cp.async)
// and conflict-free for ldmatrix (9*r mod 32 distinct, r=0..7).
#define AP 36
#define STG_BYTES   18432              // 128*36*4, per operand per stage
#define STAGE_BYTES 36864              // A + B
#define GEMM_DSMEM  73728              // 2 stages

template<int K, int NTOT, int STAGE, bool RELU, bool SCATTER>
__global__ void __launch_bounds__(256, 2) gemm_mma(const float* __restrict__ bias,
                                                   float* __restrict__ Yout)
{
    const int e = blockIdx.z;
    const int cnt = g_counts[e];
    const int row0 = blockIdx.x * 128;
    if (row0 >= cnt) return;
    const int n0 = blockIdx.y * 128;

    extern __shared__ float dsm[];
    const uint32_t smBase = smem_u32(dsm);
    __shared__ int   stok[128];
    __shared__ float swt[128];

    const int tid = threadIdx.x;
    const int lid = tid & 31, wid = tid >> 5;
    const int g = lid >> 2, tg = lid & 3;
    const int wm = wid >> 2, wn = wid & 3;        // 2 x 4 warps
    const int mb = wm * 64,  nb = wn * 32;

    const float* A  = (STAGE == 1) ? g_xg  : (STAGE == 2) ? g_h1 : g_h2;
    const float* Wt = (STAGE == 1) ? g_wT1 : (STAGE == 2) ? g_wT2 : g_wT3;
    float* Y = SCATTER ? Yout : ((STAGE == 1) ? g_h1 : g_h2);
    const float* Ab = A  + ((size_t)e * CAP_ + row0) * K;
    const float* Bb = Wt + ((size_t)e * NTOT + n0) * K;

    if (SCATTER && tid < 128) {
        int r = row0 + tid;
        stok[tid] = (r < cnt) ? g_list[e * B_ + r] : -1;
        swt[tid]  = (r < cnt) ? g_wlist[e * B_ + r] : 0.f;
    }

    // ldmatrix per-lane addresses (byte offsets from stage base)
    const int lane_row = (lid & 7) + (((lid >> 3) & 1) << 3);   // 0..15
    const int lane_k   = (lid >> 4) * 4;                        // 0 or 4
    uint32_t aAddr[4], bAddr[4];
    #pragma unroll
    for (int f = 0; f < 4; ++f)
        aAddr[f] = smBase + ((mb + f * 16 + lane_row) * AP + lane_k) * 4;
    #pragma unroll
    for (int j = 0; j < 4; ++j)
        bAddr[j] = smBase + STG_BYTES +
                   ((nb + j * 8 + (lid & 7)) * AP + ((lid >> 3) & 1) * 4) * 4;

    float acc[4][4][4];
    #pragma unroll
    for (int f = 0; f < 4; ++f)
        #pragma unroll
        for (int j = 0; j < 4; ++j)
            #pragma unroll
            for (int q = 0; q < 4; ++q) acc[f][j][q] = 0.f;

    // cp.async staging: 1024 16B chunks per operand, 4 per thread each
    auto stage_copy = [&](int buf, int kt) {
        const uint32_t sb = smBase + buf * STAGE_BYTES;
        const int k0 = kt * 32;
        #pragma unroll
        for (int q = 0; q < 4; ++q) {
            const int c = q * 256 + tid;
            const int r = c >> 3, gg = (c & 7) * 4;
            const uint32_t doff = (r * AP + gg) * 4;
            cp16(sb + doff,             Ab + (size_t)r * K + k0 + gg);
            cp16(sb + STG_BYTES + doff, Bb + (size_t)r * K + k0 + gg);
        }
    };

    constexpr int KT = K / 32;
    stage_copy(0, 0); CP_COMMIT();
    for (int kt = 0; kt < KT; ++kt) {
        const int buf = kt & 1;
        if (kt + 1 < KT) stage_copy(buf ^ 1, kt + 1);
        CP_COMMIT();
        CP_WAIT1();                 // stage kt resident
        __syncthreads();

        const uint32_t so = buf * STAGE_BYTES;
        #pragma unroll
        for (int kk = 0; kk < 32; kk += 8) {
            uint32_t af[4][4], bf[4][2];
            #pragma unroll
            for (int f = 0; f < 4; ++f) ldsm4(af[f], aAddr[f] + so + kk * 4);
            #pragma unroll
            for (int j = 0; j < 4; ++j) ldsm2(bf[j], bAddr[j] + so + kk * 4);
            #pragma unroll
            for (int f = 0; f < 4; ++f)
                #pragma unroll
                for (int j = 0; j < 4; ++j)
                    mma8(acc[f][j], af[f], bf[j]);
        }
        __syncthreads();            // buf free for reuse next+1 iteration
    }

    // ---------------- epilogue ----------------
    const float* Bbias = bias + e * NTOT + n0;
    #pragma unroll
    for (int f = 0; f < 4; ++f) {
        const int rl = mb + f * 16 + g;           // local rows rl, rl+8
        #pragma unroll
        for (int j = 0; j < 4; ++j) {
            const int c = nb + j * 8 + 2 * tg;
            const float b0 = Bbias[c], b1 = Bbias[c + 1];
            float v00 = acc[f][j][0] + b0, v01 = acc[f][j][1] + b1;
            float v10 = acc[f][j][2] + b0, v11 = acc[f][j][3] + b1;
            if (RELU) {
                v00 = fmaxf(v00, 0.f); v01 = fmaxf(v01, 0.f);
                v10 = fmaxf(v10, 0.f); v11 = fmaxf(v11, 0.f);
            }
            if (!SCATTER) {
                if (row0 + rl < cnt) {
                    float* p = Y + ((size_t)e * CAP_ + row0 + rl) * NTOT + n0 + c;
                    ((uint32_t*)p)[0] = f2tf(v00);
                    ((uint32_t*)p)[1] = f2tf(v01);
                }
                if (row0 + rl + 8 < cnt) {
                    float* p = Y + ((size_t)e * CAP_ + row0 + rl + 8) * NTOT + n0 + c;
                    ((uint32_t*)p)[0] = f2tf(v10);
                    ((uint32_t*)p)[1] = f2tf(v11);
                }
            } else {
                int t0 = stok[rl];
                if (t0 >= 0) {
                    float w0 = swt[rl];
                    atomicAdd(Yout + (size_t)t0 * D_OUT_ + n0 + c,     v00 * w0);
                    atomicAdd(Yout + (size_t)t0 * D_OUT_ + n0 + c + 1, v01 * w0);
                }
                int t1 = stok[rl + 8];
                if (t1 >= 0) {
                    float w1 = swt[rl + 8];
                    atomicAdd(Yout + (size_t)t1 * D_OUT_ + n0 + c,     v10 * w1);
                    atomicAdd(Yout + (size_t)t1 * D_OUT_ + n0 + c + 1, v11 * w1);
                }
            }
        }
    }
}

// ---------------- aux outputs ----------------
__global__ void finalize_kernel(float* __restrict__ out) {
    __shared__ float us[E_];
    const int e = threadIdx.x;
    if (e < E_) {
        float u = (float)g_counts[e] / (float)B_;
        us[e] = u;
        out[(size_t)B_ * D_OUT_ + 1 + e] = u;
    }
    __syncthreads();
    if (e == 0) {
        float s = 0.f;
        #pragma unroll
        for (int i = 0; i < E_; ++i) { float d = us[i] - (1.f / E_); s += d * d; }
        out[(size_t)B_ * D_OUT_] = (s / E_) * 0.01f;
    }
}

// ---------------- launch ----------------
extern "C" void kernel_launch(void* const* d_in, const int* in_sizes, int n_in,
                              void* d_out, int out_size) {
    const float* x   = (const float*)d_in[0];
    const float* gW1 = (const float*)d_in[1];
    const float* gb1 = (const float*)d_in[2];
    const float* gW2 = (const float*)d_in[3];
    const float* gb2 = (const float*)d_in[4];
    const float* We1 = (const float*)d_in[5];
    const float* be1 = (const float*)d_in[6];
    const float* We2 = (const float*)d_in[7];
    const float* be2 = (const float*)d_in[8];
    const float* We3 = (const float*)d_in[9];
    const float* be3 = (const float*)d_in[10];
    float* out = (float*)d_out;

    cudaFuncSetAttribute(gating_kernel, cudaFuncAttributeMaxDynamicSharedMemorySize,
                         GATE_SMEM_FLOATS * 4);
    cudaFuncSetAttribute(gemm_mma<256, 512, 1, true,  false>,
                         cudaFuncAttributeMaxDynamicSharedMemorySize, GEMM_DSMEM);
    cudaFuncSetAttribute(gemm_mma<512, 512, 2, true,  false>,
                         cudaFuncAttributeMaxDynamicSharedMemorySize, GEMM_DSMEM);
    cudaFuncSetAttribute(gemm_mma<512, 256, 3, false, true>,
                         cudaFuncAttributeMaxDynamicSharedMemorySize, GEMM_DSMEM);

    zero_kernel<<<512, 256>>>(out);
    transpose_kernel<<<dim3(256 / 32, 512 / 32, E_), 256>>>(We1, 1, 256, 512);
    transpose_kernel<<<dim3(512 / 32, 512 / 32, E_), 256>>>(We2, 2, 512, 512);
    transpose_kernel<<<dim3(512 / 32, 256 / 32, E_), 256>>>(We3, 3, 512, 256);
    gating_kernel<<<256, 256, GATE_SMEM_FLOATS * 4>>>(x, gW1, gb1, gW2, gb2);
    gather_kernel<<<dim3(CAP_ / 64, E_), 256>>>(x);

    gemm_mma<256, 512, 1, true,  false><<<dim3(CAP_ / 128, 4, E_), 256, GEMM_DSMEM>>>(be1, nullptr);
    gemm_mma<512, 512, 2, true,  false><<<dim3(CAP_ / 128, 4, E_), 256, GEMM_DSMEM>>>(be2, nullptr);
    gemm_mma<512, 256, 3, false, true ><<<dim3(CAP_ / 128, 2, E_), 256, GEMM_DSMEM>>>(be3, out);

    finalize_kernel<<<1, 32>>>(out);
}